// round 5
// baseline (speedup 1.0000x reference)
#include <cuda_runtime.h>
#include <cuda_bf16.h>

// Problem constants
#define EN    512
#define SEQ   2048
#define NBAT  4
#define NHEAD 8
#define HDIM  64
#define MTOT  (NBAT * SEQ)          // 8192
#define NSE   (NBAT * SEQ * EN)     // 4,194,304 floats per buffer

// 64 MB scratch: Q, K, V, O (pre-projection attention output)
__device__ float g_scratch[4ull * NSE];

// ---------------------------------------------------------------------------
// GEMM: C[m][n] = (sum_k A[m][k] * W[n][k] + bias[n]) * scale
// A: M x 512 row-major, W: 512 x 512 row-major (torch Linear weight layout).
// Block tile 128x128, K-tile 8, 256 threads, 8x8 per-thread micro-tile,
// register-prefetch double buffering.
// grid: (EN/128, M/128)
// ---------------------------------------------------------------------------
__global__ __launch_bounds__(256, 2)
void gemm_bias_kernel(const float* __restrict__ A, const float* __restrict__ W,
                      const float* __restrict__ bias, float* __restrict__ C,
                      float scale)
{
    __shared__ float As[8][132];   // +4 pad: conflict-free transposed stores
    __shared__ float Bs[8][132];

    const int t  = threadIdx.x;
    const int m0 = blockIdx.y << 7;
    const int n0 = blockIdx.x << 7;
    const int tx = t & 15, ty = t >> 4;
    const int ry = ty << 3, cx = tx << 3;

    // loader mapping: each thread loads one float4 of A and one of W per K-tile
    const int lr = t >> 1;           // tile row 0..127
    const int lk = (t & 1) << 2;     // k offset 0 or 4
    const float* Ap = A + (size_t)(m0 + lr) * EN + lk;
    const float* Wp = W + (size_t)(n0 + lr) * EN + lk;

    float acc[8][8];
#pragma unroll
    for (int i = 0; i < 8; i++)
#pragma unroll
        for (int j = 0; j < 8; j++) acc[i][j] = 0.0f;

    float4 aN = *(const float4*)Ap;
    float4 bN = *(const float4*)Wp;

    for (int kt = 0; kt < EN; kt += 8) {
        As[lk + 0][lr] = aN.x; As[lk + 1][lr] = aN.y;
        As[lk + 2][lr] = aN.z; As[lk + 3][lr] = aN.w;
        Bs[lk + 0][lr] = bN.x; Bs[lk + 1][lr] = bN.y;
        Bs[lk + 2][lr] = bN.z; Bs[lk + 3][lr] = bN.w;
        __syncthreads();

        if (kt + 8 < EN) {                     // prefetch next K-tile
            aN = *(const float4*)(Ap + kt + 8);
            bN = *(const float4*)(Wp + kt + 8);
        }

#pragma unroll
        for (int k = 0; k < 8; k++) {
            float a[8], b[8];
            *(float4*)(a)     = *(const float4*)&As[k][ry];
            *(float4*)(a + 4) = *(const float4*)&As[k][ry + 4];
            *(float4*)(b)     = *(const float4*)&Bs[k][cx];
            *(float4*)(b + 4) = *(const float4*)&Bs[k][cx + 4];
#pragma unroll
            for (int i = 0; i < 8; i++)
#pragma unroll
                for (int j = 0; j < 8; j++)
                    acc[i][j] += a[i] * b[j];
        }
        __syncthreads();
    }

    float bb[8];
    *(float4*)(bb)     = *(const float4*)&bias[n0 + cx];
    *(float4*)(bb + 4) = *(const float4*)&bias[n0 + cx + 4];

#pragma unroll
    for (int i = 0; i < 8; i++) {
        float* Cp = C + (size_t)(m0 + ry + i) * EN + n0 + cx;
        float4 o0 = make_float4((acc[i][0] + bb[0]) * scale,
                                (acc[i][1] + bb[1]) * scale,
                                (acc[i][2] + bb[2]) * scale,
                                (acc[i][3] + bb[3]) * scale);
        float4 o1 = make_float4((acc[i][4] + bb[4]) * scale,
                                (acc[i][5] + bb[5]) * scale,
                                (acc[i][6] + bb[6]) * scale,
                                (acc[i][7] + bb[7]) * scale);
        *(float4*)(Cp)     = o0;
        *(float4*)(Cp + 4) = o1;
    }
}

// ---------------------------------------------------------------------------
// Flash attention, fp32, causal. Br = Bc = 64, HD = 64, 256 threads (16x16),
// 4x4 micro-tiles for both S = Q K^T and O += P V.
// Smem layout: stride-64 with XOR swizzle on the minor index (quad granular)
// so transposed stores are ~2-way and all GEMM-phase LDS.128 are conflict-free.
// grid: (S/64 = 32, NBAT*NHEAD = 32), dynamic smem = 64 KB.
// ---------------------------------------------------------------------------
__device__ __forceinline__ int swz4(int maj, int min4)
{
    // float offset of the 4-aligned group (maj, min4*4) in a [64][64] buffer
    return (maj << 6) + (((min4 ^ ((maj >> 2) & 15))) << 2);
}

__global__ __launch_bounds__(256, 2)
void attention_kernel(const float* __restrict__ gQ, const float* __restrict__ gK,
                      const float* __restrict__ gV, float* __restrict__ gO)
{
    extern __shared__ float smem[];
    float* Qt = smem;           // [k][r] swizzled  (Q transposed, pre-scaled)
    float* Ks = smem + 4096;    // [k][c] swizzled  (K transposed)
    float* Vs = smem + 8192;    // [c][d] natural
    float* Pt = smem + 12288;   // [c][r] swizzled  (P transposed)

    const int t  = threadIdx.x;
    const int tx = t & 15, ty = t >> 4;
    const int ry = ty << 2, cx = tx << 2;
    // reverse order: heaviest causal blocks (large sb) launch first
    const int sb = (int)gridDim.x - 1 - (int)blockIdx.x;
    const int s0 = sb << 6;
    const int nh = blockIdx.y;
    const int n  = nh >> 3, h = nh & 7;

    const float* Qp = gQ + ((size_t)(n * SEQ + s0)) * EN + h * HDIM;
    const float* Kp = gK + (size_t)n * SEQ * EN + h * HDIM;
    const float* Vp = gV + (size_t)n * SEQ * EN + h * HDIM;

    // ---- load Q tile transposed into smem ----
#pragma unroll
    for (int i = 0; i < 4; i++) {
        int v  = t + (i << 8);
        int r  = v >> 4;           // 0..63
        int k4 = v & 15;           // float4 slot in row
        int k  = k4 << 2;
        float4 q = *(const float4*)(Qp + (size_t)r * EN + k);
        int b = swz4(k, r >> 2) + (r & 3);           // careful: swizzle per k
        Qt[swz4(k + 0, r >> 2) + (r & 3)] = q.x;
        Qt[swz4(k + 1, r >> 2) + (r & 3)] = q.y;
        Qt[swz4(k + 2, r >> 2) + (r & 3)] = q.z;
        Qt[swz4(k + 3, r >> 2) + (r & 3)] = q.w;
        (void)b;
    }

    float accO[4][4];
    float rm[4], rl[4];
#pragma unroll
    for (int i = 0; i < 4; i++) {
        rm[i] = -1e30f; rl[i] = 0.0f;
#pragma unroll
        for (int j = 0; j < 4; j++) accO[i][j] = 0.0f;
    }

    for (int kb = 0; kb <= sb; kb++) {
        __syncthreads();   // previous tile's smem reads complete before overwrite
        const float* Kt = Kp + ((size_t)(kb << 6)) * EN;
        const float* Vt = Vp + ((size_t)(kb << 6)) * EN;

        // ---- load K (transposed+swizzled) and V (natural) ----
#pragma unroll
        for (int i = 0; i < 4; i++) {
            int v  = t + (i << 8);
            int r  = v >> 4;
            int k4 = v & 15;
            int k  = k4 << 2;
            float4 kk = *(const float4*)(Kt + (size_t)r * EN + k);
            Ks[swz4(k + 0, r >> 2) + (r & 3)] = kk.x;
            Ks[swz4(k + 1, r >> 2) + (r & 3)] = kk.y;
            Ks[swz4(k + 2, r >> 2) + (r & 3)] = kk.z;
            Ks[swz4(k + 3, r >> 2) + (r & 3)] = kk.w;
            float4 vv = *(const float4*)(Vt + (size_t)r * EN + k);
            *(float4*)&Vs[(r << 6) + k] = vv;
        }
        __syncthreads();

        // ---- scores S = Q K^T (Q pre-scaled by 1/sqrt(HD)) ----
        float s[4][4];
#pragma unroll
        for (int i = 0; i < 4; i++)
#pragma unroll
            for (int j = 0; j < 4; j++) s[i][j] = 0.0f;

#pragma unroll 8
        for (int k = 0; k < 64; k++) {
            float4 a = *(const float4*)&Qt[swz4(k, ty)];
            float4 b = *(const float4*)&Ks[swz4(k, tx)];
            s[0][0] += a.x * b.x; s[0][1] += a.x * b.y; s[0][2] += a.x * b.z; s[0][3] += a.x * b.w;
            s[1][0] += a.y * b.x; s[1][1] += a.y * b.y; s[1][2] += a.y * b.z; s[1][3] += a.y * b.w;
            s[2][0] += a.z * b.x; s[2][1] += a.z * b.y; s[2][2] += a.z * b.z; s[2][3] += a.z * b.w;
            s[3][0] += a.w * b.x; s[3][1] += a.w * b.y; s[3][2] += a.w * b.z; s[3][3] += a.w * b.w;
        }

        if (kb == sb) {   // diagonal tile: causal mask (col > row)
#pragma unroll
            for (int i = 0; i < 4; i++)
#pragma unroll
                for (int j = 0; j < 4; j++)
                    if (cx + j > ry + i) s[i][j] = -1e30f;
        }

        // ---- online softmax update (row groups = 16 lanes of a half-warp) ----
#pragma unroll
        for (int i = 0; i < 4; i++) {
            float mx = fmaxf(fmaxf(s[i][0], s[i][1]), fmaxf(s[i][2], s[i][3]));
            mx = fmaxf(mx, __shfl_xor_sync(0xffffffffu, mx, 1));
            mx = fmaxf(mx, __shfl_xor_sync(0xffffffffu, mx, 2));
            mx = fmaxf(mx, __shfl_xor_sync(0xffffffffu, mx, 4));
            mx = fmaxf(mx, __shfl_xor_sync(0xffffffffu, mx, 8));
            float nm    = fmaxf(rm[i], mx);
            float alpha = __expf(rm[i] - nm);
            float ps = 0.0f;
#pragma unroll
            for (int j = 0; j < 4; j++) { s[i][j] = __expf(s[i][j] - nm); ps += s[i][j]; }
            ps += __shfl_xor_sync(0xffffffffu, ps, 1);
            ps += __shfl_xor_sync(0xffffffffu, ps, 2);
            ps += __shfl_xor_sync(0xffffffffu, ps, 4);
            ps += __shfl_xor_sync(0xffffffffu, ps, 8);
            rl[i] = rl[i] * alpha + ps;
            rm[i] = nm;
            accO[i][0] *= alpha; accO[i][1] *= alpha;
            accO[i][2] *= alpha; accO[i][3] *= alpha;
        }

        // ---- write P transposed (float4 per column) ----
#pragma unroll
        for (int j = 0; j < 4; j++) {
            int c = cx + j;
            float4 p = make_float4(s[0][j], s[1][j], s[2][j], s[3][j]);
            *(float4*)&Pt[swz4(c, ty)] = p;
        }
        __syncthreads();

        // ---- O += P V ----
#pragma unroll 8
        for (int c = 0; c < 64; c++) {
            float4 a = *(const float4*)&Pt[swz4(c, ty)];
            float4 b = *(const float4*)&Vs[(c << 6) + cx];
            accO[0][0] += a.x * b.x; accO[0][1] += a.x * b.y; accO[0][2] += a.x * b.z; accO[0][3] += a.x * b.w;
            accO[1][0] += a.y * b.x; accO[1][1] += a.y * b.y; accO[1][2] += a.y * b.z; accO[1][3] += a.y * b.w;
            accO[2][0] += a.z * b.x; accO[2][1] += a.z * b.y; accO[2][2] += a.z * b.z; accO[2][3] += a.z * b.w;
            accO[3][0] += a.w * b.x; accO[3][1] += a.w * b.y; accO[3][2] += a.w * b.z; accO[3][3] += a.w * b.w;
        }
    }

    // ---- epilogue: normalize and store (n, s, h*HD + d) layout ----
    float* Op = gO + (size_t)(n * SEQ + s0 + ry) * EN + h * HDIM + cx;
#pragma unroll
    for (int i = 0; i < 4; i++) {
        float inv = 1.0f / rl[i];
        float4 o = make_float4(accO[i][0] * inv, accO[i][1] * inv,
                               accO[i][2] * inv, accO[i][3] * inv);
        *(float4*)(Op + (size_t)i * EN) = o;
    }
}

// ---------------------------------------------------------------------------
// kernel_launch: 3 projections -> attention -> output projection.
// Scale 1/sqrt(HD) = 0.125 folded into Q projection (bias included, matching
// the reference which scales (xWq^T + bq) dot products).
// ---------------------------------------------------------------------------
extern "C" void kernel_launch(void* const* d_in, const int* in_sizes, int n_in,
                              void* d_out, int out_size)
{
    (void)in_sizes; (void)n_in; (void)out_size;

    const float* query = (const float*)d_in[0];
    const float* key   = (const float*)d_in[1];
    const float* value = (const float*)d_in[2];
    // d_in[3] = attn_mask (int32 tril) -- causal, handled analytically
    const float* Wq = (const float*)d_in[4];
    const float* bq = (const float*)d_in[5];
    const float* Wk = (const float*)d_in[6];
    const float* bk = (const float*)d_in[7];
    const float* Wv = (const float*)d_in[8];
    const float* bv = (const float*)d_in[9];
    const float* Wp = (const float*)d_in[10];
    const float* bp = (const float*)d_in[11];
    float* out = (float*)d_out;

    void* sp = nullptr;
    cudaGetSymbolAddress(&sp, g_scratch);
    float* gQ = (float*)sp;
    float* gK = gQ + NSE;
    float* gV = gK + NSE;
    float* gO = gV + NSE;

    cudaFuncSetAttribute(attention_kernel,
                         cudaFuncAttributeMaxDynamicSharedMemorySize, 65536);

    dim3 gg(EN / 128, MTOT / 128);   // (4, 64)
    gemm_bias_kernel<<<gg, 256>>>(query, Wq, bq, gQ, 0.125f);
    gemm_bias_kernel<<<gg, 256>>>(key,   Wk, bk, gK, 1.0f);
    gemm_bias_kernel<<<gg, 256>>>(value, Wv, bv, gV, 1.0f);
    attention_kernel<<<dim3(SEQ / 64, NBAT * NHEAD), 256, 65536>>>(gQ, gK, gV, gO);
    gemm_bias_kernel<<<gg, 256>>>(gO, Wp, bp, out, 1.0f);
}